// round 3
// baseline (speedup 1.0000x reference)
#include <cuda_runtime.h>
#include <math.h>

// ---- problem constants ----
#define Bb    64
#define CIMG  1024
#define NP    196
#define TL    77
#define CTXT  1024
#define Dd    512
#define Hh    8
#define HD    64

// ---- output layout (metadata order) ----
#define OFF_SCORE 0
#define OFF_ATTN  (OFF_SCORE + Bb*Bb)
#define OFF_W     (OFF_ATTN + (size_t)Bb*NP*Dd)
#define OFF_AAO   (OFF_W + (size_t)Bb*NP*TL)
#define OFF_CLS   (OFF_AAO + (size_t)Bb*Dd)
#define OFF_PROJ  (OFF_CLS + (size_t)Bb*Dd)

// ---- scratch ----
__device__ float g_proj_img[(size_t)Bb*NP*Dd];
__device__ float g_q[(size_t)Bb*NP*Dd];
__device__ float g_k[(size_t)Bb*TL*Dd];
__device__ float g_v[(size_t)Bb*TL*Dd];
__device__ float g_attn[(size_t)Bb*NP*Dd];
__device__ float g_wfull[(size_t)Bb*Hh*NP*TL];
__device__ float g_navg[(size_t)Bb*Dd];
__device__ float g_ncls[(size_t)Bb*Dd];

// ============================================================
// TF32 helpers
// ============================================================
__device__ __forceinline__ unsigned f2tf32(float x) {
    unsigned u;
    asm("cvt.rna.tf32.f32 %0, %1;" : "=r"(u) : "f"(x));
    return u;
}

#define MMA_TF32(C, Ar, Br)                                               \
    asm volatile("mma.sync.aligned.m16n8k8.row.col.f32.tf32.tf32.f32 "    \
                 "{%0,%1,%2,%3}, {%4,%5,%6,%7}, {%8,%9}, {%0,%1,%2,%3};"  \
                 : "+f"((C)[0]), "+f"((C)[1]), "+f"((C)[2]), "+f"((C)[3]) \
                 : "r"((Ar)[0]), "r"((Ar)[1]), "r"((Ar)[2]), "r"((Ar)[3]),\
                   "r"((Br)[0]), "r"((Br)[1]))

// ============================================================
// TF32 3x-split GEMM + bias:  C = A (MxK) @ W (KxN) + bias
// Block tile 128x64x16, 256 threads (8 warps: 4m x 2n), warp tile 32x32.
// AKC=true : A row-major [M,K]. AKC=false: A is [K,M] (m contiguous).
// ============================================================
#define BM 128
#define BN 64
#define BK 16
#define APAD 4
#define AROW (BK + APAD)   // 20, conflict-free fragment reads

template<bool AKC>
__global__ __launch_bounds__(256) void gemm_tf32(
    const float* __restrict__ A, long aBatch, int lda,
    const float* __restrict__ W, const float* __restrict__ bias,
    float* __restrict__ C, long cBatch, int M, int N, int K)
{
    __shared__ unsigned Ah[BM][AROW];
    __shared__ unsigned Al[BM][AROW];
    __shared__ unsigned Bh[BN][AROW];
    __shared__ unsigned Bl[BN][AROW];

    const float* Ab = A + (size_t)blockIdx.z * aBatch;
    float* Cb = C + (size_t)blockIdx.z * cBatch;
    const int m0 = blockIdx.y * BM;
    const int n0 = blockIdx.x * BN;
    const int tid  = threadIdx.x;
    const int warp = tid >> 5;
    const int lane = tid & 31;
    const int wm = (warp >> 1) * 32;   // warp m offset (0,32,64,96)
    const int wn = (warp & 1) * 32;    // warp n offset (0,32)
    const int g  = lane >> 2;          // group 0..7
    const int t  = lane & 3;           // 0..3

    float acc[2][4][4];
    #pragma unroll
    for (int i = 0; i < 2; i++)
        #pragma unroll
        for (int j = 0; j < 4; j++)
            #pragma unroll
            for (int c = 0; c < 4; c++) acc[i][j][c] = 0.f;

    for (int k0 = 0; k0 < K; k0 += BK) {
        // ---- A tile -> Ah/Al [m][k] ----
        if (AKC) {
            int r  = tid >> 1;          // 0..127
            int ks = (tid & 1) * 8;     // 0 or 8
            int m  = m0 + r;
            if (m < M) {
                const float4* ap = (const float4*)(Ab + (size_t)m * lda + (k0 + ks));
                float4 v0 = ap[0], v1 = ap[1];
                float f[8] = {v0.x,v0.y,v0.z,v0.w,v1.x,v1.y,v1.z,v1.w};
                #pragma unroll
                for (int i = 0; i < 8; i++) {
                    unsigned h = f2tf32(f[i]);
                    Ah[r][ks+i] = h;
                    Al[r][ks+i] = f2tf32(f[i] - __uint_as_float(h));
                }
            } else {
                #pragma unroll
                for (int i = 0; i < 8; i++) { Ah[r][ks+i] = 0u; Al[r][ks+i] = 0u; }
            }
        } else {
            // A[k][m], m contiguous (lda = M row length). M % 4 == 0.
            int mq = (tid & 31) * 4;    // 0..124
            int kk = tid >> 5;          // 0..7
            #pragma unroll
            for (int j = 0; j < 2; j++) {
                int kkk = kk + j * 8;
                int m = m0 + mq;
                if (m + 4 <= M) {
                    float4 v = *(const float4*)(Ab + (size_t)(k0 + kkk) * lda + m);
                    float f[4] = {v.x, v.y, v.z, v.w};
                    #pragma unroll
                    for (int i = 0; i < 4; i++) {
                        unsigned h = f2tf32(f[i]);
                        Ah[mq+i][kkk] = h;
                        Al[mq+i][kkk] = f2tf32(f[i] - __uint_as_float(h));
                    }
                } else {
                    #pragma unroll
                    for (int i = 0; i < 4; i++) { Ah[mq+i][kkk] = 0u; Al[mq+i][kkk] = 0u; }
                }
            }
        }
        // ---- B tile: W[k][n] row-major -> Bh/Bl [n][k] ----
        {
            int n  = (tid & 15) * 4;
            int kk = tid >> 4;          // 0..15
            float4 v = *(const float4*)(W + (size_t)(k0 + kk) * N + n0 + n);
            float f[4] = {v.x, v.y, v.z, v.w};
            #pragma unroll
            for (int i = 0; i < 4; i++) {
                unsigned h = f2tf32(f[i]);
                Bh[n+i][kk] = h;
                Bl[n+i][kk] = f2tf32(f[i] - __uint_as_float(h));
            }
        }
        __syncthreads();

        #pragma unroll
        for (int ks = 0; ks < BK; ks += 8) {
            unsigned ah[2][4], al[2][4], bh[4][2], bl[4][2];
            #pragma unroll
            for (int mt = 0; mt < 2; mt++) {
                int r = wm + mt * 16 + g;
                ah[mt][0] = Ah[r][ks+t];       ah[mt][1] = Ah[r+8][ks+t];
                ah[mt][2] = Ah[r][ks+4+t];     ah[mt][3] = Ah[r+8][ks+4+t];
                al[mt][0] = Al[r][ks+t];       al[mt][1] = Al[r+8][ks+t];
                al[mt][2] = Al[r][ks+4+t];     al[mt][3] = Al[r+8][ks+4+t];
            }
            #pragma unroll
            for (int nt = 0; nt < 4; nt++) {
                int c = wn + nt * 8 + g;
                bh[nt][0] = Bh[c][ks+t];  bh[nt][1] = Bh[c][ks+4+t];
                bl[nt][0] = Bl[c][ks+t];  bl[nt][1] = Bl[c][ks+4+t];
            }
            #pragma unroll
            for (int mt = 0; mt < 2; mt++)
                #pragma unroll
                for (int nt = 0; nt < 4; nt++) {
                    MMA_TF32(acc[mt][nt], ah[mt], bh[nt]);  // hi*hi
                    MMA_TF32(acc[mt][nt], ah[mt], bl[nt]);  // hi*lo
                    MMA_TF32(acc[mt][nt], al[mt], bh[nt]);  // lo*hi
                }
        }
        __syncthreads();
    }

    // ---- epilogue: +bias, store float2 pairs ----
    #pragma unroll
    for (int mt = 0; mt < 2; mt++) {
        #pragma unroll
        for (int nt = 0; nt < 4; nt++) {
            int col = n0 + wn + nt * 8 + t * 2;
            float2 bia = *(const float2*)(bias + col);
            int r0 = m0 + wm + mt * 16 + g;
            if (r0 < M) {
                float2 o0 = { acc[mt][nt][0] + bia.x, acc[mt][nt][1] + bia.y };
                *(float2*)(Cb + (size_t)r0 * N + col) = o0;
            }
            int r1 = r0 + 8;
            if (r1 < M) {
                float2 o1 = { acc[mt][nt][2] + bia.x, acc[mt][nt][3] + bia.y };
                *(float2*)(Cb + (size_t)r1 * N + col) = o1;
            }
        }
    }
}

// ============================================================
// Cross-attention per (b,h): K/V head tiles in SMEM, one warp per query row.
// ============================================================
__global__ __launch_bounds__(256) void attention_kernel()
{
    __shared__ float Ks[TL][HD + 1];
    __shared__ float Vs[TL][HD + 1];

    const int h = blockIdx.x;
    const int b = blockIdx.y;
    const int tid  = threadIdx.x;
    const int warp = tid >> 5;
    const int lane = tid & 31;

    for (int idx = tid; idx < TL * HD; idx += 256) {
        int t = idx >> 6, d = idx & 63;
        size_t g = ((size_t)(b * TL + t)) * Dd + h * HD + d;
        Ks[t][d] = g_k[g];
        Vs[t][d] = g_v[g];
    }
    __syncthreads();

    const float scale = 0.125f;

    for (int n = warp; n < NP; n += 8) {
        const float* qrow = g_q + ((size_t)(b * NP + n)) * Dd + h * HD;
        float s0 = 0.f, s1 = 0.f, s2 = 0.f;
        const bool has2 = (lane < TL - 64);
        #pragma unroll
        for (int d = 0; d < HD; d++) {
            float qd = qrow[d];
            s0 += qd * Ks[lane][d];
            s1 += qd * Ks[lane + 32][d];
            if (has2) s2 += qd * Ks[lane + 64][d];
        }
        s0 *= scale; s1 *= scale; s2 *= scale;

        float mx = fmaxf(s0, s1);
        if (has2) mx = fmaxf(mx, s2);
        #pragma unroll
        for (int o = 16; o > 0; o >>= 1)
            mx = fmaxf(mx, __shfl_xor_sync(0xffffffffu, mx, o));

        float e0 = expf(s0 - mx);
        float e1 = expf(s1 - mx);
        float e2 = has2 ? expf(s2 - mx) : 0.f;
        float sum = e0 + e1 + e2;
        #pragma unroll
        for (int o = 16; o > 0; o >>= 1)
            sum += __shfl_xor_sync(0xffffffffu, sum, o);
        float inv = 1.f / sum;
        float w0 = e0 * inv, w1 = e1 * inv, w2 = e2 * inv;

        float* wptr = g_wfull + (((size_t)(b * Hh + h) * NP) + n) * TL;
        wptr[lane]      = w0;
        wptr[lane + 32] = w1;
        if (has2) wptr[lane + 64] = w2;

        float acc0 = 0.f, acc1 = 0.f;
        #pragma unroll
        for (int t = 0; t < TL; t++) {
            int slot = t >> 5, src = t & 31;
            float wsel = (slot == 0) ? w0 : ((slot == 1) ? w1 : w2);
            float wt = __shfl_sync(0xffffffffu, wsel, src);
            acc0 += wt * Vs[t][lane];
            acc1 += wt * Vs[t][lane + 32];
        }
        size_t o = ((size_t)(b * NP + n)) * Dd + h * HD;
        g_attn[o + lane]      = acc0;
        g_attn[o + lane + 32] = acc1;
    }
}

// head-mean of attention weights
__global__ void wmean_kernel(float* __restrict__ out)
{
    size_t i = (size_t)blockIdx.x * blockDim.x + threadIdx.x;
    const size_t total = (size_t)Bb * NP * TL;
    if (i >= total) return;
    int t = i % TL;
    int n = (i / TL) % NP;
    int b = i / ((size_t)TL * NP);
    float s = 0.f;
    #pragma unroll
    for (int h = 0; h < Hh; h++)
        s += g_wfull[(((size_t)(b * Hh + h) * NP) + n) * TL + t];
    out[i] = s * (1.f / Hh);
}

// mean over rows: src [B, R, D] -> dst [B, D]
__global__ void rowmean_kernel(const float* __restrict__ src,
                               float* __restrict__ dst, int R)
{
    int b = blockIdx.x, d = threadIdx.x;
    const float* p = src + (size_t)b * R * Dd + d;
    float acc = 0.f;
    for (int r = 0; r < R; r++) acc += p[(size_t)r * Dd];
    dst[(size_t)b * Dd + d] = acc / (float)R;
}

// L2-normalize 64 vectors of length 512
__global__ void l2norm_kernel(const float* __restrict__ src,
                              float* __restrict__ dst)
{
    __shared__ float red[256];
    int b = blockIdx.x, tid = threadIdx.x;
    const float* p = src + (size_t)b * Dd;
    float v0 = p[tid], v1 = p[tid + 256];
    red[tid] = v0 * v0 + v1 * v1;
    __syncthreads();
    for (int o = 128; o > 0; o >>= 1) {
        if (tid < o) red[tid] += red[tid + o];
        __syncthreads();
    }
    float inv = 1.f / fmaxf(sqrtf(red[0]), 1e-8f);
    float* q = dst + (size_t)b * Dd;
    q[tid] = v0 * inv;
    q[tid + 256] = v1 * inv;
}

// score[i][j] = navg[i] . ncls[j]
__global__ void score_kernel(float* __restrict__ score)
{
    __shared__ float qi[Dd];
    int i = blockIdx.x, tid = threadIdx.x;
    #pragma unroll
    for (int c = 0; c < Dd / 64; c++)
        qi[tid + c * 64] = g_navg[(size_t)i * Dd + tid + c * 64];
    __syncthreads();
    const float* cj = g_ncls + (size_t)tid * Dd;
    float acc = 0.f;
    #pragma unroll 8
    for (int d = 0; d < Dd; d++) acc += qi[d] * cj[d];
    score[(size_t)i * Bb + tid] = acc;
}

// ============================================================
extern "C" void kernel_launch(void* const* d_in, const int* in_sizes, int n_in,
                              void* d_out, int out_size)
{
    const float* image = (const float*)d_in[0];
    const float* text  = (const float*)d_in[1];
    const float* Wi = (const float*)d_in[2];  const float* bi = (const float*)d_in[3];
    const float* Wt = (const float*)d_in[4];  const float* bt = (const float*)d_in[5];
    const float* Wq = (const float*)d_in[6];  const float* bq = (const float*)d_in[7];
    const float* Wk = (const float*)d_in[8];  const float* bk = (const float*)d_in[9];
    const float* Wv = (const float*)d_in[10]; const float* bv = (const float*)d_in[11];
    const float* Wo = (const float*)d_in[12]; const float* bo = (const float*)d_in[13];
    float* out = (float*)d_out;

    float *p_img, *p_q, *p_k, *p_v, *p_attn, *p_navg, *p_ncls;
    cudaGetSymbolAddress((void**)&p_img,  g_proj_img);
    cudaGetSymbolAddress((void**)&p_q,    g_q);
    cudaGetSymbolAddress((void**)&p_k,    g_k);
    cudaGetSymbolAddress((void**)&p_v,    g_v);
    cudaGetSymbolAddress((void**)&p_attn, g_attn);
    cudaGetSymbolAddress((void**)&p_navg, g_navg);
    cudaGetSymbolAddress((void**)&p_ncls, g_ncls);

    float* out_proj = out + OFF_PROJ;
    float* out_attn = out + OFF_ATTN;

    // 1) proj_img = image^T @ Wi + bi   (batched, A = [C, NP] per batch)
    {
        dim3 g(Dd / BN, (NP + BM - 1) / BM, Bb);
        gemm_tf32<false><<<g, 256>>>(image, (long)CIMG * NP, NP,
                                     Wi, bi, p_img, (long)NP * Dd, NP, Dd, CIMG);
    }
    // 2) proj_txt = text @ Wt + bt : single GEMM M = B*T
    {
        dim3 g(Dd / BN, (Bb * TL + BM - 1) / BM, 1);
        gemm_tf32<true><<<g, 256>>>(text, 0, CTXT,
                                    Wt, bt, out_proj, 0, Bb * TL, Dd, CTXT);
    }
    // 3) q = proj_img @ Wq + bq : M = B*N (12544 = 98 full tiles)
    {
        dim3 g(Dd / BN, (Bb * NP + BM - 1) / BM, 1);
        gemm_tf32<true><<<g, 256>>>(p_img, 0, Dd,
                                    Wq, bq, p_q, 0, Bb * NP, Dd, Dd);
    }
    // 4) k, 5) v : M = B*T
    {
        dim3 g(Dd / BN, (Bb * TL + BM - 1) / BM, 1);
        gemm_tf32<true><<<g, 256>>>(out_proj, 0, Dd,
                                    Wk, bk, p_k, 0, Bb * TL, Dd, Dd);
        gemm_tf32<true><<<g, 256>>>(out_proj, 0, Dd,
                                    Wv, bv, p_v, 0, Bb * TL, Dd, Dd);
    }
    // 6) attention
    {
        dim3 g(Hh, Bb);
        attention_kernel<<<g, 256>>>();
    }
    // 7) attn_output = attn @ Wo + bo
    {
        dim3 g(Dd / BN, (Bb * NP + BM - 1) / BM, 1);
        gemm_tf32<true><<<g, 256>>>(p_attn, 0, Dd,
                                    Wo, bo, out_attn, 0, Bb * NP, Dd, Dd);
    }
    // 8) head-averaged weights
    {
        size_t total = (size_t)Bb * NP * TL;
        wmean_kernel<<<(unsigned)((total + 255) / 256), 256>>>(out + OFF_W);
    }
    // 9) avg_attn_output, 10) cls_embeddings
    rowmean_kernel<<<Bb, Dd>>>(out_attn, out + OFF_AAO, NP);
    rowmean_kernel<<<Bb, Dd>>>(out_proj, out + OFF_CLS, TL);
    // 11) cosine-similarity score matrix
    l2norm_kernel<<<Bb, 256>>>(out + OFF_AAO, p_navg);
    l2norm_kernel<<<Bb, 256>>>(out + OFF_CLS, p_ncls);
    score_kernel<<<Bb, 64>>>(out + OFF_SCORE);
}